// round 14
// baseline (speedup 1.0000x reference)
#include <cuda_runtime.h>
#include <cuda_fp16.h>

#define NU 80000
#define NI 30000
#define NT 110000   // NU + NI
#define DD 64
#define NNZ_ADJ 2000000
#define NNZ_MM  300000

#define ADJ_CAP 64
#define MM_CAP  48

// out layout (float offsets)
#define OFF_UG   0
#define OFF_IG   (NU*DD)
#define OFF_IMG  (OFF_IG + NI*DD)
#define OFF_TXT  (OFF_IMG + NI*DD)
#define OFF_H    (OFF_TXT + NI*DD)

// ---------------- scratch ----------------
__device__ __half g_ego_h[NT*DD];    // fp16 [user_emb ; item_emb]
__device__ __half g_cur1_h[NT*DD];   // fp16 layer-1 adj output
__device__ __half g_ih_h[2*NI*DD];   // fp16 [ipre ; hnorm] for item tcq
__device__ float  g_q[2*NI];         // modal query outputs
__device__ float  g_q2[2*NI];        // item query outputs

__device__ int  g_cnt[NT + 2*NI];
__device__ int2 g_adj_pairs[(size_t)NT * ADJ_CAP];
__device__ int2 g_img_pairs[(size_t)NI * MM_CAP];
__device__ int2 g_txt_pairs[(size_t)NI * MM_CAP];

// ---------------- bucket build ----------------
__device__ __forceinline__ void bucket4(int4 r, int4 c, float4 v,
                                        int* __restrict__ counts, int2* __restrict__ pairs,
                                        int cap) {
    int p0 = atomicAdd(&counts[r.x], 1);
    int p1 = atomicAdd(&counts[r.y], 1);
    int p2 = atomicAdd(&counts[r.z], 1);
    int p3 = atomicAdd(&counts[r.w], 1);
    if (p0 < cap) pairs[(size_t)r.x * cap + p0] = make_int2(c.x, __float_as_int(v.x));
    if (p1 < cap) pairs[(size_t)r.y * cap + p1] = make_int2(c.y, __float_as_int(v.y));
    if (p2 < cap) pairs[(size_t)r.z * cap + p2] = make_int2(c.z, __float_as_int(v.z));
    if (p3 < cap) pairs[(size_t)r.w * cap + p3] = make_int2(c.w, __float_as_int(v.w));
}

__device__ __forceinline__ void bucket8(const int4* r, const int4* c, const float4* v, int e,
                                        int* __restrict__ counts, int2* __restrict__ pairs,
                                        int cap) {
    int4 r0 = r[2*e], r1 = r[2*e+1];
    int4 c0 = c[2*e], c1 = c[2*e+1];
    float4 v0 = v[2*e], v1 = v[2*e+1];
    bucket4(r0, c0, v0, counts, pairs, cap);
    bucket4(r1, c1, v1, counts, pairs, cap);
}

#define TA8 (NNZ_ADJ/8)
#define TM8 (NNZ_MM/8)
#define CVT_B ((NT*(DD/4) + 255)/256)
#define BKT_B ((TA8 + 2*TM8 + 255)/256)

// ---------------- K1: fp16 ego conversion + bucket builds (fused) ----------------
__global__ __launch_bounds__(256) void k1_prep_kernel(
        const float4* __restrict__ ue, const float4* __restrict__ ie,
        const int4* __restrict__ ar, const int4* __restrict__ ac, const float4* __restrict__ av,
        const int4* __restrict__ ir, const int4* __restrict__ ic, const float4* __restrict__ iv,
        const int4* __restrict__ tr, const int4* __restrict__ tc, const float4* __restrict__ tv) {
    if (blockIdx.x < CVT_B) {
        int i = blockIdx.x * blockDim.x + threadIdx.x;
        if (i >= NT * (DD / 4)) return;
        float4 v = (i < NU * (DD / 4)) ? ue[i] : ie[i - NU * (DD / 4)];
        __half2 h01 = __floats2half2_rn(v.x, v.y);
        __half2 h23 = __floats2half2_rn(v.z, v.w);
        uint2 u;
        u.x = *reinterpret_cast<unsigned*>(&h01);
        u.y = *reinterpret_cast<unsigned*>(&h23);
        reinterpret_cast<uint2*>(g_ego_h)[i] = u;
    } else {
        int t = (blockIdx.x - CVT_B) * blockDim.x + threadIdx.x;
        if (t < TA8) {
            bucket8(ar, ac, av, t, g_cnt, g_adj_pairs, ADJ_CAP);
        } else if (t < TA8 + TM8) {
            bucket8(ir, ic, iv, t - TA8, g_cnt + NT, g_img_pairs, MM_CAP);
        } else if (t < TA8 + 2 * TM8) {
            bucket8(tr, tc, tv, t - TA8 - TM8, g_cnt + NT + NI, g_txt_pairs, MM_CAP);
        }
    }
}

// ============================================================================
// Quarter-warp fp16 gather: each 8-lane quarter owns one 128B fp16 row
// (lane ql owns 8 halfs = uint4). 4 independent rows per warp => ~16 loads in
// flight. All quarters loop to the warp-wide cnt_max with zero-padded pairs
// so full-mask width-8 shfls stay converged.
// ============================================================================
__device__ __forceinline__ void gather_row_quad_h(const int2* __restrict__ p_my, int cnt_my,
                                                  int cnt_max, const __half* __restrict__ x,
                                                  int ql, float4& a0, float4& a1) {
    a0 = make_float4(0.f, 0.f, 0.f, 0.f);
    a1 = make_float4(0.f, 0.f, 0.f, 0.f);
    for (int base = 0; base < cnt_max; base += 8) {
        int j = base + ql;
        int2 pr = (j < cnt_my) ? p_my[j] : make_int2(0, 0);   // pad: col 0, val 0.0f
        int m4 = (min(cnt_max - base, 8) + 3) & ~3;
        for (int k = 0; k < m4; k += 4) {
#pragma unroll
            for (int kk = 0; kk < 4; kk++) {
                int   c = __shfl_sync(0xffffffffu, pr.x, k + kk, 8);
                float v = __int_as_float(__shfl_sync(0xffffffffu, pr.y, k + kk, 8));
                uint4 u = __ldg(reinterpret_cast<const uint4*>(x + (size_t)c * DD) + ql);
                float2 f0 = __half22float2(*reinterpret_cast<__half2*>(&u.x));
                float2 f1 = __half22float2(*reinterpret_cast<__half2*>(&u.y));
                float2 f2 = __half22float2(*reinterpret_cast<__half2*>(&u.z));
                float2 f3 = __half22float2(*reinterpret_cast<__half2*>(&u.w));
                a0.x = fmaf(v, f0.x, a0.x); a0.y = fmaf(v, f0.y, a0.y);
                a0.z = fmaf(v, f1.x, a0.z); a0.w = fmaf(v, f1.y, a0.w);
                a1.x = fmaf(v, f2.x, a1.x); a1.y = fmaf(v, f2.y, a1.y);
                a1.z = fmaf(v, f3.x, a1.z); a1.w = fmaf(v, f3.y, a1.w);
            }
        }
    }
}

__device__ __forceinline__ int warp_cnt_max4(int cnt) {
    int c = max(cnt, __shfl_xor_sync(0xffffffffu, cnt, 8));
    return max(c, __shfl_xor_sync(0xffffffffu, c, 16));
}

__device__ __forceinline__ void store_half8(__half* __restrict__ dst, int ql,
                                            float4 a0, float4 a1) {
    __half2 h0 = __floats2half2_rn(a0.x, a0.y);
    __half2 h1 = __floats2half2_rn(a0.z, a0.w);
    __half2 h2 = __floats2half2_rn(a1.x, a1.y);
    __half2 h3 = __floats2half2_rn(a1.z, a1.w);
    uint4 u;
    u.x = *reinterpret_cast<unsigned*>(&h0);
    u.y = *reinterpret_cast<unsigned*>(&h1);
    u.z = *reinterpret_cast<unsigned*>(&h2);
    u.w = *reinterpret_cast<unsigned*>(&h3);
    reinterpret_cast<uint4*>(dst)[ql] = u;
}

// ---------------- K2: adj layer 1 + modal gathers (4 rows/warp) ----------------
#define ADJ_W (NT / 4)     // 27500 warps for adj1
#define MOD_W (2 * NI / 4) // 15000 warps for modal

__global__ __launch_bounds__(256) void k2_gather_kernel(float* __restrict__ out_img,
                                                        float* __restrict__ out_txt) {
    int w = (blockIdx.x * blockDim.x + threadIdx.x) >> 5;
    int lane = threadIdx.x & 31;
    int q = lane >> 3, ql = lane & 7;
    if (w < ADJ_W) {
        int row = w * 4 + q;
        int cnt = min(g_cnt[row], ADJ_CAP);
        int cmax = warp_cnt_max4(cnt);
        float4 a0, a1;
        gather_row_quad_h(g_adj_pairs + (size_t)row * ADJ_CAP, cnt, cmax, g_ego_h, ql, a0, a1);
        store_half8(g_cur1_h + (size_t)row * DD, ql, a0, a1);
    } else if (w < ADJ_W + MOD_W) {
        int mrow = (w - ADJ_W) * 4 + q;           // NI % 4 == 0 => no img/txt straddle
        bool is_img = mrow < NI;
        int row = is_img ? mrow : mrow - NI;
        int cnt = min(is_img ? g_cnt[NT + row] : g_cnt[NT + NI + row], MM_CAP);
        int cmax = warp_cnt_max4(cnt);
        const int2* p = (is_img ? g_img_pairs : g_txt_pairs) + (size_t)row * MM_CAP;
        float4 a0, a1;
        gather_row_quad_h(p, cnt, cmax, g_ego_h + (size_t)NU * DD, ql, a0, a1);
        float* dst = (is_img ? out_img : out_txt) + (size_t)row * DD;
        reinterpret_cast<float4*>(dst)[ql * 2]     = a0;
        reinterpret_cast<float4*>(dst)[ql * 2 + 1] = a1;
    }
}

// ============================================================================
// Tensor-core query body: 8 rows/warp, 64 rows/block.
// ============================================================================
__device__ __forceinline__ unsigned f2h2(float x, float y) {
    __half2 h = __floats2half2_rn(x, y);
    return *reinterpret_cast<unsigned*>(&h);
}

__device__ __forceinline__ float ftanh(float x) {
    x = fminf(fmaxf(x, -15.f), 15.f);
    float e = __expf(2.f * x);
    return (e - 1.f) / (e + 1.f);
}

__device__ __forceinline__ void mma16816(float& c0, float& c1, float& c2, float& c3,
                                         unsigned a0, unsigned a1, unsigned a2, unsigned a3,
                                         unsigned b0, unsigned b1) {
    asm volatile("mma.sync.aligned.m16n8k16.row.col.f32.f16.f16.f32 "
                 "{%0,%1,%2,%3}, {%4,%5,%6,%7}, {%8,%9}, {%0,%1,%2,%3};"
                 : "+f"(c0), "+f"(c1), "+f"(c2), "+f"(c3)
                 : "r"(a0), "r"(a1), "r"(a2), "r"(a3), "r"(b0), "r"(b1));
}

#define WT_STRIDE 72
#define TCQ_ROWS_PER_BLOCK 64
#define TCQ_BLOCKS ((2*NI + TCQ_ROWS_PER_BLOCK - 1) / TCQ_ROWS_PER_BLOCK)   // 938

template <typename XT>
__device__ void tcq_body(const XT* __restrict__ X, int nrows,
                         const float* __restrict__ W, const float* __restrict__ b,
                         const float* __restrict__ w2, float* __restrict__ qout, int bid) {
    __shared__ __half sWt[64 * WT_STRIDE];
    __shared__ float sb[64];
    __shared__ float sw2[64];
    for (int i = threadIdx.x; i < 4096; i += 256) {
        int k = i >> 6, n = i & 63;                    // coalesced read of W
        sWt[n * WT_STRIDE + k] = __float2half(W[i]);
    }
    if (threadIdx.x < 64) { sb[threadIdx.x] = b[threadIdx.x]; sw2[threadIdx.x] = w2[threadIdx.x]; }
    __syncthreads();

    int w = threadIdx.x >> 5, lane = threadIdx.x & 31;
    int gr = lane >> 2, tig = lane & 3;
    int base = bid * TCQ_ROWS_PER_BLOCK + w * 8;
    if (base >= nrows) return;
    int r0 = base + gr;                                // nrows % 8 == 0 => valid

    unsigned ra[4][2];
#pragma unroll
    for (int kt = 0; kt < 4; kt++) {
        if (sizeof(XT) == 4) {
            const float* x0 = reinterpret_cast<const float*>(X) + (size_t)r0 * 64 + kt * 16 + tig * 2;
            float2 f0 = *reinterpret_cast<const float2*>(x0);
            float2 f2 = *reinterpret_cast<const float2*>(x0 + 8);
            ra[kt][0] = f2h2(f0.x, f0.y);
            ra[kt][1] = f2h2(f2.x, f2.y);
        } else {
            const __half* x0 = reinterpret_cast<const __half*>(X) + (size_t)r0 * 64 + kt * 16 + tig * 2;
            ra[kt][0] = *reinterpret_cast<const unsigned*>(x0);
            ra[kt][1] = *reinterpret_cast<const unsigned*>(x0 + 8);
        }
    }

    float q0 = 0.f;
#pragma unroll
    for (int nt = 0; nt < 8; nt++) {
        float c0 = 0.f, c1 = 0.f, c2 = 0.f, c3 = 0.f;
        int n = nt * 8 + gr;
#pragma unroll
        for (int kt = 0; kt < 4; kt++) {
            int k0 = kt * 16 + tig * 2;
            unsigned b0 = *reinterpret_cast<const unsigned*>(sWt + n * WT_STRIDE + k0);
            unsigned b1 = *reinterpret_cast<const unsigned*>(sWt + n * WT_STRIDE + k0 + 8);
            mma16816(c0, c1, c2, c3, ra[kt][0], 0u, ra[kt][1], 0u, b0, b1);
        }
        int col0 = nt * 8 + tig * 2, col1 = col0 + 1;
        q0 += ftanh(c0 + sb[col0]) * sw2[col0] + ftanh(c1 + sb[col1]) * sw2[col1];
    }
    q0 += __shfl_xor_sync(0xffffffffu, q0, 1);
    q0 += __shfl_xor_sync(0xffffffffu, q0, 2);
    if (tig == 0) qout[r0] = q0;
}

// ---------------- adj2 body (quarter-warp gather + final averaging) ----------------
__device__ void adj2_body(const float4* __restrict__ ue, const float4* __restrict__ ie,
                          float* __restrict__ ug, int bid) {
    int w = (bid * 256 + (int)threadIdx.x) >> 5;
    int lane = threadIdx.x & 31;
    int q = lane >> 3, ql = lane & 7;
    if (w >= ADJ_W) return;
    int row = w * 4 + q;
    int cnt = min(g_cnt[row], ADJ_CAP);
    int cmax = warp_cnt_max4(cnt);
    float4 s0, s1;
    gather_row_quad_h(g_adj_pairs + (size_t)row * ADJ_CAP, cnt, cmax, g_cur1_h, ql, s0, s1);
    const float kk = 1.f / 3.f;
    // c1 (fp16) for this row: lane owns halfs [ql*8, ql*8+8)
    uint4 u = reinterpret_cast<const uint4*>(g_cur1_h + (size_t)row * DD)[ql];
    float2 c0 = __half22float2(*reinterpret_cast<__half2*>(&u.x));
    float2 c1 = __half22float2(*reinterpret_cast<__half2*>(&u.y));
    float2 c2 = __half22float2(*reinterpret_cast<__half2*>(&u.z));
    float2 c3 = __half22float2(*reinterpret_cast<__half2*>(&u.w));
    // e (fp32 exact): lane owns floats [ql*8, ql*8+8) = two float4s
    const float4* esrc = (row < NU) ? (ue + (size_t)row * 16) : (ie + (size_t)(row - NU) * 16);
    float4 e0 = esrc[ql * 2], e1 = esrc[ql * 2 + 1];
    float4 r0 = make_float4((e0.x + c0.x + s0.x) * kk, (e0.y + c0.y + s0.y) * kk,
                            (e0.z + c1.x + s0.z) * kk, (e0.w + c1.y + s0.w) * kk);
    float4 r1 = make_float4((e1.x + c2.x + s1.x) * kk, (e1.y + c2.y + s1.y) * kk,
                            (e1.z + c3.x + s1.z) * kk, (e1.w + c3.y + s1.w) * kk);
    if (row < NU) {
        reinterpret_cast<float4*>(ug + (size_t)row * DD)[ql * 2]     = r0;
        reinterpret_cast<float4*>(ug + (size_t)row * DD)[ql * 2 + 1] = r1;
    } else {
        store_half8(g_ih_h + (size_t)(row - NU) * DD, ql, r0, r1);   // ipre (fp16)
    }
}

// ---------------- K3: tcq1 (blocks [0,TCQ_BLOCKS)) || adj2 (rest) ----------------
#define ADJ2_B ((ADJ_W + 7) / 8)   // 3438 blocks (8 warps/block)

__global__ __launch_bounds__(256) void k3_fused_kernel(const float* __restrict__ Xmod,
                                                       const float* __restrict__ Wq1,
                                                       const float* __restrict__ bq1,
                                                       const float* __restrict__ wq2,
                                                       const float4* __restrict__ ue,
                                                       const float4* __restrict__ ie,
                                                       float* __restrict__ ug) {
    if (blockIdx.x < TCQ_BLOCKS) {
        tcq_body<float>(Xmod, 2 * NI, Wq1, bq1, wq2, g_q, blockIdx.x);
    } else {
        adj2_body(ue, ie, ug, blockIdx.x - TCQ_BLOCKS);
    }
}

// ---------------- K5: tcq2 standalone (fp16 input) ----------------
__global__ __launch_bounds__(256) void tcq2_kernel(const float* __restrict__ Wc1,
                                                   const float* __restrict__ bc1,
                                                   const float* __restrict__ wc2) {
    tcq_body<__half>(g_ih_h, 2 * NI, Wc1, bc1, wc2, g_q2, blockIdx.x);
}

// ---------------- K4: combine_mm (hnorm stored fp16) ----------------
__global__ __launch_bounds__(256) void combine_mm_kernel(const float* __restrict__ img,
                                                         const float* __restrict__ txt,
                                                         float* __restrict__ h_out) {
    int w = (blockIdx.x * blockDim.x + threadIdx.x) >> 5;
    int lane = threadIdx.x & 31;
    int half = lane >> 4, hl = lane & 15;
    int item = w * 2 + half;
    if (item >= NI) return;
    float qi = g_q[item], qt = g_q[NI + item];
    float m = fmaxf(qi, qt);
    float e0 = __expf(qi - m), e1 = __expf(qt - m);
    float sinv = 1.f / (e0 + e1);
    float w0 = e0 * sinv, w1 = e1 * sinv;
    float4 iv = reinterpret_cast<const float4*>(img + (size_t)item * DD)[hl];
    float4 tv = reinterpret_cast<const float4*>(txt + (size_t)item * DD)[hl];
    float4 h = make_float4(w0 * iv.x + w1 * tv.x, w0 * iv.y + w1 * tv.y,
                           w0 * iv.z + w1 * tv.z, w0 * iv.w + w1 * tv.w);
    float ss = h.x * h.x + h.y * h.y + h.z * h.z + h.w * h.w;
#pragma unroll
    for (int o = 1; o < 16; o <<= 1) ss += __shfl_xor_sync(0xffffffffu, ss, o, 16);
    float rinv = 1.f / fmaxf(sqrtf(ss), 1e-12f);
    reinterpret_cast<float4*>(h_out + (size_t)item * DD)[hl] = h;
    float4 hn = make_float4(h.x * rinv, h.y * rinv, h.z * rinv, h.w * rinv);
    __half2 h01 = __floats2half2_rn(hn.x, hn.y);
    __half2 h23 = __floats2half2_rn(hn.z, hn.w);
    uint2 uo;
    uo.x = *reinterpret_cast<unsigned*>(&h01);
    uo.y = *reinterpret_cast<unsigned*>(&h23);
    reinterpret_cast<uint2*>(g_ih_h + (size_t)(NI + item) * DD)[hl] = uo;
}

// ---------------- K6: combine_item (fp16 sources, q2) ----------------
__global__ __launch_bounds__(256) void combine_item_kernel(float* __restrict__ ig) {
    int idx = blockIdx.x * blockDim.x + threadIdx.x;      // one float4 of output per thread
    if (idx >= NI * (DD / 4)) return;
    int item = idx >> 4;
    float q0 = g_q2[item], q1 = g_q2[NI + item];
    float m = fmaxf(q0, q1);
    float e0 = __expf(q0 - m), e1 = __expf(q1 - m);
    float sinv = 1.f / (e0 + e1);
    float w0 = e0 * sinv, w1 = e1 * sinv;
    uint2 ua = reinterpret_cast<const uint2*>(g_ih_h)[idx];
    uint2 un = reinterpret_cast<const uint2*>(g_ih_h)[NI * (DD / 4) + idx];
    float2 a01 = __half22float2(*reinterpret_cast<__half2*>(&ua.x));
    float2 a23 = __half22float2(*reinterpret_cast<__half2*>(&ua.y));
    float2 n01 = __half22float2(*reinterpret_cast<__half2*>(&un.x));
    float2 n23 = __half22float2(*reinterpret_cast<__half2*>(&un.y));
    float4 r = make_float4(w0 * a01.x + w1 * n01.x, w0 * a01.y + w1 * n01.y,
                           w0 * a23.x + w1 * n23.x, w0 * a23.y + w1 * n23.y);
    reinterpret_cast<float4*>(ig)[idx] = r;
}

extern "C" void kernel_launch(void* const* d_in, const int* in_sizes, int n_in,
                              void* d_out, int out_size) {
    const float* user_emb = (const float*)d_in[0];
    const float* item_emb = (const float*)d_in[1];
    const float* Wq1 = (const float*)d_in[2];
    const float* bq1 = (const float*)d_in[3];
    const float* wq2 = (const float*)d_in[4];
    const float* Wc1 = (const float*)d_in[5];
    const float* bc1 = (const float*)d_in[6];
    const float* wc2 = (const float*)d_in[7];
    const float* adj_vals = (const float*)d_in[8];
    const float* img_vals = (const float*)d_in[9];
    const float* txt_vals = (const float*)d_in[10];
    const int* adj_rows = (const int*)d_in[11];
    const int* adj_cols = (const int*)d_in[12];
    const int* img_rows = (const int*)d_in[13];
    const int* img_cols = (const int*)d_in[14];
    const int* txt_rows = (const int*)d_in[15];
    const int* txt_cols = (const int*)d_in[16];

    float* out = (float*)d_out;
    float* out_ug  = out + OFF_UG;
    float* out_ig  = out + OFF_IG;
    float* out_img = out + OFF_IMG;
    float* out_txt = out + OFF_TXT;
    float* out_h   = out + OFF_H;

    const int T = 256;

    int* cnt; cudaGetSymbolAddress((void**)&cnt, g_cnt);

    // 0. zero counters
    cudaMemsetAsync(cnt, 0, (NT + 2 * NI) * sizeof(int));

    // 1. fp16 ego conversion + bucket builds (8 edges/thread)
    k1_prep_kernel<<<CVT_B + BKT_B, T>>>(
        (const float4*)user_emb, (const float4*)item_emb,
        (const int4*)adj_rows, (const int4*)adj_cols, (const float4*)adj_vals,
        (const int4*)img_rows, (const int4*)img_cols, (const float4*)img_vals,
        (const int4*)txt_rows, (const int4*)txt_cols, (const float4*)txt_vals);

    // 2. adj layer 1 + modal gathers (4 rows/warp)
    {
        int nwarps = ADJ_W + MOD_W;
        k2_gather_kernel<<<(nwarps + 7) / 8, T>>>(out_img, out_txt);
    }

    // 3. modal queries (tcq blocks first) || adj layer 2 + final averaging
    k3_fused_kernel<<<TCQ_BLOCKS + ADJ2_B, T>>>(out_img, Wq1, bq1, wq2,
                                                (const float4*)user_emb,
                                                (const float4*)item_emb, out_ug);

    // 4. modal softmax mix -> h (fp32), hnorm (fp16)
    {
        int nwarps = (NI + 1) / 2;
        combine_mm_kernel<<<(nwarps + 7) / 8, T>>>(out_img, out_txt, out_h);
    }

    // 5. item queries over fp16 [ipre ; hnorm]
    tcq2_kernel<<<TCQ_BLOCKS, T>>>(Wc1, bc1, wc2);

    // 6. item cross-attention mix -> ig
    {
        int n = NI * (DD / 4);
        combine_item_kernel<<<(n + T - 1) / T, T>>>(out_ig);
    }

    (void)in_sizes; (void)n_in; (void)out_size;
}

// round 15
// speedup vs baseline: 1.0237x; 1.0237x over previous
#include <cuda_runtime.h>
#include <cuda_fp16.h>

#define NU 80000
#define NI 30000
#define NT 110000   // NU + NI
#define DD 64
#define NNZ_ADJ 2000000
#define NNZ_MM  300000

#define ADJ_CAP 64
#define MM_CAP  48

// out layout (float offsets)
#define OFF_UG   0
#define OFF_IG   (NU*DD)
#define OFF_IMG  (OFF_IG + NI*DD)
#define OFF_TXT  (OFF_IMG + NI*DD)
#define OFF_H    (OFF_TXT + NI*DD)

// ---------------- scratch ----------------
__device__ __half g_ego_h[NT*DD];    // fp16 [user_emb ; item_emb]
__device__ __half g_cur1_h[NT*DD];   // fp16 layer-1 adj output
__device__ __half g_mod_h[2*NI*DD];  // fp16 [img_e ; txt_e] copy for tcq1/combine_mm
__device__ __half g_ih_h[2*NI*DD];   // fp16 [ipre ; hnorm] for item tcq
__device__ float  g_q[2*NI];         // modal query outputs
__device__ float  g_q2[2*NI];        // item query outputs

__device__ int  g_cnt[NT + 2*NI];
__device__ int2 g_adj_pairs[(size_t)NT * ADJ_CAP];
__device__ int2 g_img_pairs[(size_t)NI * MM_CAP];
__device__ int2 g_txt_pairs[(size_t)NI * MM_CAP];

// ---------------- bucket build ----------------
__device__ __forceinline__ void bucket4(int4 r, int4 c, float4 v,
                                        int* __restrict__ counts, int2* __restrict__ pairs,
                                        int cap) {
    int p0 = atomicAdd(&counts[r.x], 1);
    int p1 = atomicAdd(&counts[r.y], 1);
    int p2 = atomicAdd(&counts[r.z], 1);
    int p3 = atomicAdd(&counts[r.w], 1);
    if (p0 < cap) pairs[(size_t)r.x * cap + p0] = make_int2(c.x, __float_as_int(v.x));
    if (p1 < cap) pairs[(size_t)r.y * cap + p1] = make_int2(c.y, __float_as_int(v.y));
    if (p2 < cap) pairs[(size_t)r.z * cap + p2] = make_int2(c.z, __float_as_int(v.z));
    if (p3 < cap) pairs[(size_t)r.w * cap + p3] = make_int2(c.w, __float_as_int(v.w));
}

__device__ __forceinline__ void bucket8(const int4* r, const int4* c, const float4* v, int e,
                                        int* __restrict__ counts, int2* __restrict__ pairs,
                                        int cap) {
    int4 r0 = r[2*e], r1 = r[2*e+1];
    int4 c0 = c[2*e], c1 = c[2*e+1];
    float4 v0 = v[2*e], v1 = v[2*e+1];
    bucket4(r0, c0, v0, counts, pairs, cap);
    bucket4(r1, c1, v1, counts, pairs, cap);
}

#define TA8 (NNZ_ADJ/8)
#define TM8 (NNZ_MM/8)
#define CVT_B ((NT*(DD/4) + 255)/256)
#define BKT_B ((TA8 + 2*TM8 + 255)/256)

// ---------------- K1: fp16 ego conversion + bucket builds (fused) ----------------
__global__ __launch_bounds__(256) void k1_prep_kernel(
        const float4* __restrict__ ue, const float4* __restrict__ ie,
        const int4* __restrict__ ar, const int4* __restrict__ ac, const float4* __restrict__ av,
        const int4* __restrict__ ir, const int4* __restrict__ ic, const float4* __restrict__ iv,
        const int4* __restrict__ tr, const int4* __restrict__ tc, const float4* __restrict__ tv) {
    if (blockIdx.x < CVT_B) {
        int i = blockIdx.x * blockDim.x + threadIdx.x;
        if (i >= NT * (DD / 4)) return;
        float4 v = (i < NU * (DD / 4)) ? ue[i] : ie[i - NU * (DD / 4)];
        __half2 h01 = __floats2half2_rn(v.x, v.y);
        __half2 h23 = __floats2half2_rn(v.z, v.w);
        uint2 u;
        u.x = *reinterpret_cast<unsigned*>(&h01);
        u.y = *reinterpret_cast<unsigned*>(&h23);
        reinterpret_cast<uint2*>(g_ego_h)[i] = u;
    } else {
        int t = (blockIdx.x - CVT_B) * blockDim.x + threadIdx.x;
        if (t < TA8) {
            bucket8(ar, ac, av, t, g_cnt, g_adj_pairs, ADJ_CAP);
        } else if (t < TA8 + TM8) {
            bucket8(ir, ic, iv, t - TA8, g_cnt + NT, g_img_pairs, MM_CAP);
        } else if (t < TA8 + 2 * TM8) {
            bucket8(tr, tc, tv, t - TA8 - TM8, g_cnt + NT + NI, g_txt_pairs, MM_CAP);
        }
    }
}

// ---------------- paired-row fp16 gather (R12-proven) ----------------
__device__ __forceinline__ float4 gather_row_pair_h(const int2* __restrict__ p_my, int cnt_my,
                                                    int cnt_max, const __half* __restrict__ x,
                                                    int hl) {
    float4 a = make_float4(0.f, 0.f, 0.f, 0.f);
    for (int base = 0; base < cnt_max; base += 16) {
        int j = base + hl;
        int2 pr = (j < cnt_my) ? p_my[j] : make_int2(0, 0);
        int m4 = (min(cnt_max - base, 16) + 3) & ~3;
        for (int k = 0; k < m4; k += 4) {
#pragma unroll
            for (int kk = 0; kk < 4; kk++) {
                int   c = __shfl_sync(0xffffffffu, pr.x, k + kk, 16);
                float v = __int_as_float(__shfl_sync(0xffffffffu, pr.y, k + kk, 16));
                uint2 u = __ldg(reinterpret_cast<const uint2*>(x + (size_t)c * DD) + hl);
                __half2 h01 = *reinterpret_cast<__half2*>(&u.x);
                __half2 h23 = *reinterpret_cast<__half2*>(&u.y);
                float2 f01 = __half22float2(h01);
                float2 f23 = __half22float2(h23);
                a.x = fmaf(v, f01.x, a.x);
                a.y = fmaf(v, f01.y, a.y);
                a.z = fmaf(v, f23.x, a.z);
                a.w = fmaf(v, f23.y, a.w);
            }
        }
    }
    return a;
}

__device__ __forceinline__ void store_half4(__half* __restrict__ dst, int hl, float4 a) {
    __half2 h01 = __floats2half2_rn(a.x, a.y);
    __half2 h23 = __floats2half2_rn(a.z, a.w);
    uint2 u;
    u.x = *reinterpret_cast<unsigned*>(&h01);
    u.y = *reinterpret_cast<unsigned*>(&h23);
    reinterpret_cast<uint2*>(dst)[hl] = u;
}

// ---------------- K2: adj layer 1 + modal gathers ----------------
__global__ __launch_bounds__(256) void k2_gather_kernel(float* __restrict__ out_img,
                                                        float* __restrict__ out_txt) {
    int w = (blockIdx.x * blockDim.x + threadIdx.x) >> 5;
    int lane = threadIdx.x & 31;
    int half = lane >> 4, hl = lane & 15;
    if (w < NT / 2) {
        int row = w * 2 + half;
        int cnt = min(g_cnt[row], ADJ_CAP);
        int cmax = max(cnt, __shfl_xor_sync(0xffffffffu, cnt, 16));
        float4 a = gather_row_pair_h(g_adj_pairs + (size_t)row * ADJ_CAP, cnt, cmax, g_ego_h, hl);
        store_half4(g_cur1_h + (size_t)row * DD, hl, a);
    } else if (w < NT / 2 + NI) {
        int mrow = (w - NT / 2) * 2 + half;
        bool is_img = mrow < NI;
        int row = is_img ? mrow : mrow - NI;
        int cnt = min(is_img ? g_cnt[NT + row] : g_cnt[NT + NI + row], MM_CAP);
        int cmax = max(cnt, __shfl_xor_sync(0xffffffffu, cnt, 16));
        const int2* p = (is_img ? g_img_pairs : g_txt_pairs) + (size_t)row * MM_CAP;
        float4 a = gather_row_pair_h(p, cnt, cmax, g_ego_h + (size_t)NU * DD, hl);
        float* dst = (is_img ? out_img : out_txt) + (size_t)row * DD;
        reinterpret_cast<float4*>(dst)[hl] = a;                       // fp32 output
        store_half4(g_mod_h + (size_t)mrow * DD, hl, a);              // fp16 copy for tcq1/cmm
    }
}

// ============================================================================
// Tensor-core query body (fp16 input): 8 rows/warp, 64 rows/block.
// ============================================================================
__device__ __forceinline__ float ftanh(float x) {
    x = fminf(fmaxf(x, -15.f), 15.f);
    float e = __expf(2.f * x);
    return (e - 1.f) / (e + 1.f);
}

__device__ __forceinline__ void mma16816(float& c0, float& c1, float& c2, float& c3,
                                         unsigned a0, unsigned a1, unsigned a2, unsigned a3,
                                         unsigned b0, unsigned b1) {
    asm volatile("mma.sync.aligned.m16n8k16.row.col.f32.f16.f16.f32 "
                 "{%0,%1,%2,%3}, {%4,%5,%6,%7}, {%8,%9}, {%0,%1,%2,%3};"
                 : "+f"(c0), "+f"(c1), "+f"(c2), "+f"(c3)
                 : "r"(a0), "r"(a1), "r"(a2), "r"(a3), "r"(b0), "r"(b1));
}

#define WT_STRIDE 72
#define TCQ_ROWS_PER_BLOCK 64
#define TCQ_BLOCKS ((2*NI + TCQ_ROWS_PER_BLOCK - 1) / TCQ_ROWS_PER_BLOCK)   // 938

__device__ void tcq_body(const __half* __restrict__ X, int nrows,
                         const float* __restrict__ W, const float* __restrict__ b,
                         const float* __restrict__ w2, float* __restrict__ qout, int bid) {
    __shared__ __half sWt[64 * WT_STRIDE];
    __shared__ float sb[64];
    __shared__ float sw2[64];
    for (int i = threadIdx.x; i < 4096; i += 256) {
        int k = i >> 6, n = i & 63;                    // coalesced read of W
        sWt[n * WT_STRIDE + k] = __float2half(W[i]);
    }
    if (threadIdx.x < 64) { sb[threadIdx.x] = b[threadIdx.x]; sw2[threadIdx.x] = w2[threadIdx.x]; }
    __syncthreads();

    int w = threadIdx.x >> 5, lane = threadIdx.x & 31;
    int gr = lane >> 2, tig = lane & 3;
    int base = bid * TCQ_ROWS_PER_BLOCK + w * 8;
    if (base >= nrows) return;
    int r0 = base + gr;                                // nrows % 8 == 0 => valid

    unsigned ra[4][2];
#pragma unroll
    for (int kt = 0; kt < 4; kt++) {
        const __half* x0 = X + (size_t)r0 * 64 + kt * 16 + tig * 2;
        ra[kt][0] = *reinterpret_cast<const unsigned*>(x0);       // 4B aligned (tig*2 even)
        ra[kt][1] = *reinterpret_cast<const unsigned*>(x0 + 8);
    }

    float q0 = 0.f;
#pragma unroll
    for (int nt = 0; nt < 8; nt++) {
        float c0 = 0.f, c1 = 0.f, c2 = 0.f, c3 = 0.f;
        int n = nt * 8 + gr;
#pragma unroll
        for (int kt = 0; kt < 4; kt++) {
            int k0 = kt * 16 + tig * 2;
            unsigned b0 = *reinterpret_cast<const unsigned*>(sWt + n * WT_STRIDE + k0);
            unsigned b1 = *reinterpret_cast<const unsigned*>(sWt + n * WT_STRIDE + k0 + 8);
            mma16816(c0, c1, c2, c3, ra[kt][0], 0u, ra[kt][1], 0u, b0, b1);
        }
        int col0 = nt * 8 + tig * 2, col1 = col0 + 1;
        q0 += ftanh(c0 + sb[col0]) * sw2[col0] + ftanh(c1 + sb[col1]) * sw2[col1];
    }
    q0 += __shfl_xor_sync(0xffffffffu, q0, 1);
    q0 += __shfl_xor_sync(0xffffffffu, q0, 2);
    if (tig == 0) qout[r0] = q0;
}

// ---------------- adj2 body (paired-row gather + final averaging) ----------------
__device__ void adj2_body(const float4* __restrict__ ue, const float4* __restrict__ ie,
                          float* __restrict__ ug, int bid) {
    int w = (bid * 256 + (int)threadIdx.x) >> 5;
    int lane = threadIdx.x & 31;
    int half = lane >> 4, hl = lane & 15;
    if (w >= NT / 2) return;
    int row = w * 2 + half;
    int cnt = min(g_cnt[row], ADJ_CAP);
    int cmax = max(cnt, __shfl_xor_sync(0xffffffffu, cnt, 16));
    float4 s = gather_row_pair_h(g_adj_pairs + (size_t)row * ADJ_CAP, cnt, cmax, g_cur1_h, hl);
    const float kk = 1.f / 3.f;
    uint2 u = reinterpret_cast<const uint2*>(g_cur1_h + (size_t)row * DD)[hl];
    float2 c01 = __half22float2(*reinterpret_cast<__half2*>(&u.x));
    float2 c23 = __half22float2(*reinterpret_cast<__half2*>(&u.y));
    float4 e = (row < NU) ? ue[row * (DD / 4) + hl]
                          : ie[(row - NU) * (DD / 4) + hl];
    float4 r = make_float4((e.x + c01.x + s.x) * kk, (e.y + c01.y + s.y) * kk,
                           (e.z + c23.x + s.z) * kk, (e.w + c23.y + s.w) * kk);
    if (row < NU) {
        reinterpret_cast<float4*>(ug + (size_t)row * DD)[hl] = r;
    } else {
        store_half4(g_ih_h + (size_t)(row - NU) * DD, hl, r);   // ipre (fp16)
    }
}

// ---------------- K3: tcq1 (blocks [0,TCQ_BLOCKS)) || adj2 (rest) ----------------
__global__ __launch_bounds__(256) void k3_fused_kernel(const float* __restrict__ Wq1,
                                                       const float* __restrict__ bq1,
                                                       const float* __restrict__ wq2,
                                                       const float4* __restrict__ ue,
                                                       const float4* __restrict__ ie,
                                                       float* __restrict__ ug) {
    if (blockIdx.x < TCQ_BLOCKS) {
        tcq_body(g_mod_h, 2 * NI, Wq1, bq1, wq2, g_q, blockIdx.x);
    } else {
        adj2_body(ue, ie, ug, blockIdx.x - TCQ_BLOCKS);
    }
}

// ---------------- K5: tcq2 standalone (fp16 input) ----------------
__global__ __launch_bounds__(256) void tcq2_kernel(const float* __restrict__ Wc1,
                                                   const float* __restrict__ bc1,
                                                   const float* __restrict__ wc2) {
    tcq_body(g_ih_h, 2 * NI, Wc1, bc1, wc2, g_q2, blockIdx.x);
}

// ---------------- K4: combine_mm (fp16 modal reads; h fp32, hnorm fp16) ----------------
__global__ __launch_bounds__(256) void combine_mm_kernel(float* __restrict__ h_out) {
    int w = (blockIdx.x * blockDim.x + threadIdx.x) >> 5;
    int lane = threadIdx.x & 31;
    int half = lane >> 4, hl = lane & 15;
    int item = w * 2 + half;
    if (item >= NI) return;
    float qi = g_q[item], qt = g_q[NI + item];
    float m = fmaxf(qi, qt);
    float e0 = __expf(qi - m), e1 = __expf(qt - m);
    float sinv = 1.f / (e0 + e1);
    float w0 = e0 * sinv, w1 = e1 * sinv;
    uint2 ui = reinterpret_cast<const uint2*>(g_mod_h + (size_t)item * DD)[hl];
    uint2 ut = reinterpret_cast<const uint2*>(g_mod_h + (size_t)(NI + item) * DD)[hl];
    float2 i01 = __half22float2(*reinterpret_cast<__half2*>(&ui.x));
    float2 i23 = __half22float2(*reinterpret_cast<__half2*>(&ui.y));
    float2 t01 = __half22float2(*reinterpret_cast<__half2*>(&ut.x));
    float2 t23 = __half22float2(*reinterpret_cast<__half2*>(&ut.y));
    float4 h = make_float4(w0 * i01.x + w1 * t01.x, w0 * i01.y + w1 * t01.y,
                           w0 * i23.x + w1 * t23.x, w0 * i23.y + w1 * t23.y);
    float ss = h.x * h.x + h.y * h.y + h.z * h.z + h.w * h.w;
#pragma unroll
    for (int o = 1; o < 16; o <<= 1) ss += __shfl_xor_sync(0xffffffffu, ss, o, 16);
    float rinv = 1.f / fmaxf(sqrtf(ss), 1e-12f);
    reinterpret_cast<float4*>(h_out + (size_t)item * DD)[hl] = h;
    float4 hn = make_float4(h.x * rinv, h.y * rinv, h.z * rinv, h.w * rinv);
    store_half4(g_ih_h + (size_t)(NI + item) * DD, hl, hn);
}

// ---------------- K6: combine_item (fp16 sources, q2) ----------------
__global__ __launch_bounds__(256) void combine_item_kernel(float* __restrict__ ig) {
    int idx = blockIdx.x * blockDim.x + threadIdx.x;      // one float4 of output per thread
    if (idx >= NI * (DD / 4)) return;
    int item = idx >> 4;
    float q0 = g_q2[item], q1 = g_q2[NI + item];
    float m = fmaxf(q0, q1);
    float e0 = __expf(q0 - m), e1 = __expf(q1 - m);
    float sinv = 1.f / (e0 + e1);
    float w0 = e0 * sinv, w1 = e1 * sinv;
    uint2 ua = reinterpret_cast<const uint2*>(g_ih_h)[idx];
    uint2 un = reinterpret_cast<const uint2*>(g_ih_h)[NI * (DD / 4) + idx];
    float2 a01 = __half22float2(*reinterpret_cast<__half2*>(&ua.x));
    float2 a23 = __half22float2(*reinterpret_cast<__half2*>(&ua.y));
    float2 n01 = __half22float2(*reinterpret_cast<__half2*>(&un.x));
    float2 n23 = __half22float2(*reinterpret_cast<__half2*>(&un.y));
    float4 r = make_float4(w0 * a01.x + w1 * n01.x, w0 * a01.y + w1 * n01.y,
                           w0 * a23.x + w1 * n23.x, w0 * a23.y + w1 * n23.y);
    reinterpret_cast<float4*>(ig)[idx] = r;
}

extern "C" void kernel_launch(void* const* d_in, const int* in_sizes, int n_in,
                              void* d_out, int out_size) {
    const float* user_emb = (const float*)d_in[0];
    const float* item_emb = (const float*)d_in[1];
    const float* Wq1 = (const float*)d_in[2];
    const float* bq1 = (const float*)d_in[3];
    const float* wq2 = (const float*)d_in[4];
    const float* Wc1 = (const float*)d_in[5];
    const float* bc1 = (const float*)d_in[6];
    const float* wc2 = (const float*)d_in[7];
    const float* adj_vals = (const float*)d_in[8];
    const float* img_vals = (const float*)d_in[9];
    const float* txt_vals = (const float*)d_in[10];
    const int* adj_rows = (const int*)d_in[11];
    const int* adj_cols = (const int*)d_in[12];
    const int* img_rows = (const int*)d_in[13];
    const int* img_cols = (const int*)d_in[14];
    const int* txt_rows = (const int*)d_in[15];
    const int* txt_cols = (const int*)d_in[16];

    float* out = (float*)d_out;
    float* out_ug  = out + OFF_UG;
    float* out_ig  = out + OFF_IG;
    float* out_img = out + OFF_IMG;
    float* out_txt = out + OFF_TXT;
    float* out_h   = out + OFF_H;

    const int T = 256;

    int* cnt; cudaGetSymbolAddress((void**)&cnt, g_cnt);

    // 0. zero counters
    cudaMemsetAsync(cnt, 0, (NT + 2 * NI) * sizeof(int));

    // 1. fp16 ego conversion + bucket builds (8 edges/thread)
    k1_prep_kernel<<<CVT_B + BKT_B, T>>>(
        (const float4*)user_emb, (const float4*)item_emb,
        (const int4*)adj_rows, (const int4*)adj_cols, (const float4*)adj_vals,
        (const int4*)img_rows, (const int4*)img_cols, (const float4*)img_vals,
        (const int4*)txt_rows, (const int4*)txt_cols, (const float4*)txt_vals);

    // 2. adj layer 1 + modal gathers (paired-row, fp16 sources; modal also writes fp16 copy)
    {
        int nwarps = NT / 2 + NI;
        k2_gather_kernel<<<(nwarps + 7) / 8, T>>>(out_img, out_txt);
    }

    // 3. modal queries over fp16 copy (tcq blocks first) || adj layer 2 + final averaging
    {
        int adj_blocks = (NT / 2 + 7) / 8;   // 6875
        k3_fused_kernel<<<TCQ_BLOCKS + adj_blocks, T>>>(Wq1, bq1, wq2,
                                                        (const float4*)user_emb,
                                                        (const float4*)item_emb, out_ug);
    }

    // 4. modal softmax mix -> h (fp32), hnorm (fp16)
    {
        int nwarps = (NI + 1) / 2;
        combine_mm_kernel<<<(nwarps + 7) / 8, T>>>(out_h);
    }

    // 5. item queries over fp16 [ipre ; hnorm]
    tcq2_kernel<<<TCQ_BLOCKS, T>>>(Wc1, bc1, wc2);

    // 6. item cross-attention mix -> ig
    {
        int n = NI * (DD / 4);
        combine_item_kernel<<<(n + T - 1) / T, T>>>(out_ig);
    }

    (void)in_sizes; (void)n_in; (void)out_size;
}

// round 16
// speedup vs baseline: 1.0633x; 1.0387x over previous
#include <cuda_runtime.h>
#include <cuda_fp16.h>

#define NU 80000
#define NI 30000
#define NT 110000   // NU + NI
#define DD 64
#define NNZ_ADJ 2000000
#define NNZ_MM  300000

#define ADJ_CAP 64
#define MM_CAP  48

// out layout (float offsets)
#define OFF_UG   0
#define OFF_IG   (NU*DD)
#define OFF_IMG  (OFF_IG + NI*DD)
#define OFF_TXT  (OFF_IMG + NI*DD)
#define OFF_H    (OFF_TXT + NI*DD)

// ---------------- scratch ----------------
__device__ __half g_ego_h[NT*DD];    // fp16 [user_emb ; item_emb]
__device__ __half g_cur1_h[NT*DD];   // fp16 layer-1 adj output
__device__ __half g_ih_h[NI*DD];     // fp16 ipre for item tcq
__device__ float  g_q[2*NI];         // modal query outputs

__device__ int  g_cnt[NT + 2*NI];
__device__ int2 g_adj_pairs[(size_t)NT * ADJ_CAP];
__device__ int2 g_img_pairs[(size_t)NI * MM_CAP];
__device__ int2 g_txt_pairs[(size_t)NI * MM_CAP];

// ---------------- bucket build (R12 config: 4 edges/thread) ----------------
__device__ __forceinline__ void bucket4(int4 r, int4 c, float4 v,
                                        int* __restrict__ counts, int2* __restrict__ pairs,
                                        int cap) {
    int p0 = atomicAdd(&counts[r.x], 1);
    int p1 = atomicAdd(&counts[r.y], 1);
    int p2 = atomicAdd(&counts[r.z], 1);
    int p3 = atomicAdd(&counts[r.w], 1);
    if (p0 < cap) pairs[(size_t)r.x * cap + p0] = make_int2(c.x, __float_as_int(v.x));
    if (p1 < cap) pairs[(size_t)r.y * cap + p1] = make_int2(c.y, __float_as_int(v.y));
    if (p2 < cap) pairs[(size_t)r.z * cap + p2] = make_int2(c.z, __float_as_int(v.z));
    if (p3 < cap) pairs[(size_t)r.w * cap + p3] = make_int2(c.w, __float_as_int(v.w));
}

#define TA (NNZ_ADJ/4)
#define TM (NNZ_MM/4)
#define CVT_B ((NT*(DD/4) + 255)/256)
#define BKT_B ((TA + 2*TM + 255)/256)

// ---------------- K1: fp16 ego conversion + bucket builds (fused) ----------------
__global__ __launch_bounds__(256) void k1_prep_kernel(
        const float4* __restrict__ ue, const float4* __restrict__ ie,
        const int4* __restrict__ ar, const int4* __restrict__ ac, const float4* __restrict__ av,
        const int4* __restrict__ ir, const int4* __restrict__ ic, const float4* __restrict__ iv,
        const int4* __restrict__ tr, const int4* __restrict__ tc, const float4* __restrict__ tv) {
    if (blockIdx.x < CVT_B) {
        int i = blockIdx.x * blockDim.x + threadIdx.x;
        if (i >= NT * (DD / 4)) return;
        float4 v = (i < NU * (DD / 4)) ? ue[i] : ie[i - NU * (DD / 4)];
        __half2 h01 = __floats2half2_rn(v.x, v.y);
        __half2 h23 = __floats2half2_rn(v.z, v.w);
        uint2 u;
        u.x = *reinterpret_cast<unsigned*>(&h01);
        u.y = *reinterpret_cast<unsigned*>(&h23);
        reinterpret_cast<uint2*>(g_ego_h)[i] = u;
    } else {
        int t = (blockIdx.x - CVT_B) * blockDim.x + threadIdx.x;
        if (t < TA) {
            bucket4(ar[t], ac[t], av[t], g_cnt, g_adj_pairs, ADJ_CAP);
        } else if (t < TA + TM) {
            int e = t - TA;
            bucket4(ir[e], ic[e], iv[e], g_cnt + NT, g_img_pairs, MM_CAP);
        } else if (t < TA + 2 * TM) {
            int e = t - TA - TM;
            bucket4(tr[e], tc[e], tv[e], g_cnt + NT + NI, g_txt_pairs, MM_CAP);
        }
    }
}

// ---------------- paired-row fp16 gather (R12-proven) ----------------
__device__ __forceinline__ float4 gather_row_pair_h(const int2* __restrict__ p_my, int cnt_my,
                                                    int cnt_max, const __half* __restrict__ x,
                                                    int hl) {
    float4 a = make_float4(0.f, 0.f, 0.f, 0.f);
    for (int base = 0; base < cnt_max; base += 16) {
        int j = base + hl;
        int2 pr = (j < cnt_my) ? p_my[j] : make_int2(0, 0);
        int m4 = (min(cnt_max - base, 16) + 3) & ~3;
        for (int k = 0; k < m4; k += 4) {
#pragma unroll
            for (int kk = 0; kk < 4; kk++) {
                int   c = __shfl_sync(0xffffffffu, pr.x, k + kk, 16);
                float v = __int_as_float(__shfl_sync(0xffffffffu, pr.y, k + kk, 16));
                uint2 u = __ldg(reinterpret_cast<const uint2*>(x + (size_t)c * DD) + hl);
                __half2 h01 = *reinterpret_cast<__half2*>(&u.x);
                __half2 h23 = *reinterpret_cast<__half2*>(&u.y);
                float2 f01 = __half22float2(h01);
                float2 f23 = __half22float2(h23);
                a.x = fmaf(v, f01.x, a.x);
                a.y = fmaf(v, f01.y, a.y);
                a.z = fmaf(v, f23.x, a.z);
                a.w = fmaf(v, f23.y, a.w);
            }
        }
    }
    return a;
}

__device__ __forceinline__ void store_half4(__half* __restrict__ dst, int hl, float4 a) {
    __half2 h01 = __floats2half2_rn(a.x, a.y);
    __half2 h23 = __floats2half2_rn(a.z, a.w);
    uint2 u;
    u.x = *reinterpret_cast<unsigned*>(&h01);
    u.y = *reinterpret_cast<unsigned*>(&h23);
    reinterpret_cast<uint2*>(dst)[hl] = u;
}

// ---------------- K2: adj layer 1 + modal gathers ----------------
__global__ __launch_bounds__(256) void k2_gather_kernel(float* __restrict__ out_img,
                                                        float* __restrict__ out_txt) {
    int w = (blockIdx.x * blockDim.x + threadIdx.x) >> 5;
    int lane = threadIdx.x & 31;
    int half = lane >> 4, hl = lane & 15;
    if (w < NT / 2) {
        int row = w * 2 + half;
        int cnt = min(g_cnt[row], ADJ_CAP);
        int cmax = max(cnt, __shfl_xor_sync(0xffffffffu, cnt, 16));
        float4 a = gather_row_pair_h(g_adj_pairs + (size_t)row * ADJ_CAP, cnt, cmax, g_ego_h, hl);
        store_half4(g_cur1_h + (size_t)row * DD, hl, a);
    } else if (w < NT / 2 + NI) {
        int mrow = (w - NT / 2) * 2 + half;
        bool is_img = mrow < NI;
        int row = is_img ? mrow : mrow - NI;
        int cnt = min(is_img ? g_cnt[NT + row] : g_cnt[NT + NI + row], MM_CAP);
        int cmax = max(cnt, __shfl_xor_sync(0xffffffffu, cnt, 16));
        const int2* p = (is_img ? g_img_pairs : g_txt_pairs) + (size_t)row * MM_CAP;
        float4 a = gather_row_pair_h(p, cnt, cmax, g_ego_h + (size_t)NU * DD, hl);
        float* dst = (is_img ? out_img : out_txt) + (size_t)row * DD;
        reinterpret_cast<float4*>(dst)[hl] = a;
    }
}

// ============================================================================
// MMA helpers
// ============================================================================
__device__ __forceinline__ unsigned f2h2(float x, float y) {
    __half2 h = __floats2half2_rn(x, y);
    return *reinterpret_cast<unsigned*>(&h);
}

__device__ __forceinline__ float ftanh(float x) {
    x = fminf(fmaxf(x, -15.f), 15.f);
    float e = __expf(2.f * x);
    return (e - 1.f) / (e + 1.f);
}

__device__ __forceinline__ void mma16816(float& c0, float& c1, float& c2, float& c3,
                                         unsigned a0, unsigned a1, unsigned a2, unsigned a3,
                                         unsigned b0, unsigned b1) {
    asm volatile("mma.sync.aligned.m16n8k16.row.col.f32.f16.f16.f32 "
                 "{%0,%1,%2,%3}, {%4,%5,%6,%7}, {%8,%9}, {%0,%1,%2,%3};"
                 : "+f"(c0), "+f"(c1), "+f"(c2), "+f"(c3)
                 : "r"(a0), "r"(a1), "r"(a2), "r"(a3), "r"(b0), "r"(b1));
}

#define WT_STRIDE 72
#define TCQ_ROWS_PER_BLOCK 64
#define TCQ_BLOCKS ((2*NI + TCQ_ROWS_PER_BLOCK - 1) / TCQ_ROWS_PER_BLOCK)   // 938

// ---------------- tcq1 body: modal queries over fp32 img|txt -> g_q ----------------
__device__ void tcq_body_f32(const float* __restrict__ X, int nrows,
                             const float* __restrict__ W, const float* __restrict__ b,
                             const float* __restrict__ w2, float* __restrict__ qout, int bid) {
    __shared__ __half sWt[64 * WT_STRIDE];
    __shared__ float sb[64];
    __shared__ float sw2[64];
    for (int i = threadIdx.x; i < 4096; i += 256) {
        int k = i >> 6, n = i & 63;
        sWt[n * WT_STRIDE + k] = __float2half(W[i]);
    }
    if (threadIdx.x < 64) { sb[threadIdx.x] = b[threadIdx.x]; sw2[threadIdx.x] = w2[threadIdx.x]; }
    __syncthreads();

    int w = threadIdx.x >> 5, lane = threadIdx.x & 31;
    int gr = lane >> 2, tig = lane & 3;
    int base = bid * TCQ_ROWS_PER_BLOCK + w * 8;
    if (base >= nrows) return;
    int r0 = base + gr;

    unsigned ra[4][2];
#pragma unroll
    for (int kt = 0; kt < 4; kt++) {
        const float* x0 = X + (size_t)r0 * 64 + kt * 16 + tig * 2;
        float2 f0 = *reinterpret_cast<const float2*>(x0);
        float2 f2 = *reinterpret_cast<const float2*>(x0 + 8);
        ra[kt][0] = f2h2(f0.x, f0.y);
        ra[kt][1] = f2h2(f2.x, f2.y);
    }

    float q0 = 0.f;
#pragma unroll
    for (int nt = 0; nt < 8; nt++) {
        float c0 = 0.f, c1 = 0.f, c2 = 0.f, c3 = 0.f;
        int n = nt * 8 + gr;
#pragma unroll
        for (int kt = 0; kt < 4; kt++) {
            int k0 = kt * 16 + tig * 2;
            unsigned b0 = *reinterpret_cast<const unsigned*>(sWt + n * WT_STRIDE + k0);
            unsigned b1 = *reinterpret_cast<const unsigned*>(sWt + n * WT_STRIDE + k0 + 8);
            mma16816(c0, c1, c2, c3, ra[kt][0], 0u, ra[kt][1], 0u, b0, b1);
        }
        int col0 = nt * 8 + tig * 2, col1 = col0 + 1;
        q0 += ftanh(c0 + sb[col0]) * sw2[col0] + ftanh(c1 + sb[col1]) * sw2[col1];
    }
    q0 += __shfl_xor_sync(0xffffffffu, q0, 1);
    q0 += __shfl_xor_sync(0xffffffffu, q0, 2);
    if (tig == 0) qout[r0] = q0;
}

// ---------------- adj2 body (paired-row gather + final averaging) ----------------
__device__ void adj2_body(const float4* __restrict__ ue, const float4* __restrict__ ie,
                          float* __restrict__ ug, int bid) {
    int w = (bid * 256 + (int)threadIdx.x) >> 5;
    int lane = threadIdx.x & 31;
    int half = lane >> 4, hl = lane & 15;
    if (w >= NT / 2) return;
    int row = w * 2 + half;
    int cnt = min(g_cnt[row], ADJ_CAP);
    int cmax = max(cnt, __shfl_xor_sync(0xffffffffu, cnt, 16));
    float4 s = gather_row_pair_h(g_adj_pairs + (size_t)row * ADJ_CAP, cnt, cmax, g_cur1_h, hl);
    const float kk = 1.f / 3.f;
    uint2 u = reinterpret_cast<const uint2*>(g_cur1_h + (size_t)row * DD)[hl];
    float2 c01 = __half22float2(*reinterpret_cast<__half2*>(&u.x));
    float2 c23 = __half22float2(*reinterpret_cast<__half2*>(&u.y));
    float4 e = (row < NU) ? ue[row * (DD / 4) + hl]
                          : ie[(row - NU) * (DD / 4) + hl];
    float4 r = make_float4((e.x + c01.x + s.x) * kk, (e.y + c01.y + s.y) * kk,
                           (e.z + c23.x + s.z) * kk, (e.w + c23.y + s.w) * kk);
    if (row < NU) {
        reinterpret_cast<float4*>(ug + (size_t)row * DD)[hl] = r;
    } else {
        store_half4(g_ih_h + (size_t)(row - NU) * DD, hl, r);   // ipre (fp16)
    }
}

// ---------------- K3: tcq1 (blocks [0,TCQ_BLOCKS)) || adj2 (rest) ----------------
__global__ __launch_bounds__(256) void k3_fused_kernel(const float* __restrict__ Xmod,
                                                       const float* __restrict__ Wq1,
                                                       const float* __restrict__ bq1,
                                                       const float* __restrict__ wq2,
                                                       const float4* __restrict__ ue,
                                                       const float4* __restrict__ ie,
                                                       float* __restrict__ ug) {
    if (blockIdx.x < TCQ_BLOCKS) {
        tcq_body_f32(Xmod, 2 * NI, Wq1, bq1, wq2, g_q, blockIdx.x);
    } else {
        adj2_body(ue, ie, ug, blockIdx.x - TCQ_BLOCKS);
    }
}

// ============================================================================
// K4 (fused tail): warp owns 8 items through all three stages.
//   stage 1: combine_mm — softmax(g_q) mix of img/txt -> h (out); hnorm -> smem
//   stage 2: m16n8k16 tcq, rows 0-7 = ipre (g_ih_h), rows 8-15 = hnorm (smem)
//   stage 3: softmax(q_ipre,q_hnorm) mix of ipre/hnorm -> ig
// 128 threads (4 warps) x 32 items per block; 938 blocks. All cross-stage
// dependencies are warp-private (same items) => __syncwarp only.
// ============================================================================
#define K4_ITEMS 32
#define K4_BLOCKS ((NI + K4_ITEMS - 1) / K4_ITEMS)   // 938
#define HN_STRIDE 72   // padded hnorm smem row (halfs): conflict-free frag loads

__global__ __launch_bounds__(128) void k4_tail_kernel(const float* __restrict__ img,
                                                      const float* __restrict__ txt,
                                                      const float* __restrict__ Wc1,
                                                      const float* __restrict__ bc1,
                                                      const float* __restrict__ wc2,
                                                      float* __restrict__ h_out,
                                                      float* __restrict__ ig) {
    __shared__ __half sWt[64 * WT_STRIDE];
    __shared__ float sb[64];
    __shared__ float sw2[64];
    __shared__ __half sHn[4][8 * HN_STRIDE];
    for (int i = threadIdx.x; i < 4096; i += 128) {
        int k = i >> 6, n = i & 63;
        sWt[n * WT_STRIDE + k] = __float2half(Wc1[i]);
    }
    if (threadIdx.x < 64) { sb[threadIdx.x] = bc1[threadIdx.x]; sw2[threadIdx.x] = wc2[threadIdx.x]; }
    __syncthreads();

    int w = threadIdx.x >> 5, lane = threadIdx.x & 31;
    int base = blockIdx.x * K4_ITEMS + w * 8;   // NI % 8 == 0 => warps all-or-nothing
    if (base >= NI) return;

    // ---- stage 1: combine_mm for items base..base+7 ----
#pragma unroll
    for (int t = 0; t < 8; t++) {
        int item = base + t;
        float qi = g_q[item], qt = g_q[NI + item];
        float m = fmaxf(qi, qt);
        float e0 = __expf(qi - m), e1 = __expf(qt - m);
        float sinv = 1.f / (e0 + e1);
        float w0 = e0 * sinv, w1 = e1 * sinv;
        float2 iv = reinterpret_cast<const float2*>(img + (size_t)item * DD)[lane];
        float2 tv = reinterpret_cast<const float2*>(txt + (size_t)item * DD)[lane];
        float2 h = make_float2(w0 * iv.x + w1 * tv.x, w0 * iv.y + w1 * tv.y);
        float ss = h.x * h.x + h.y * h.y;
#pragma unroll
        for (int o = 1; o < 32; o <<= 1) ss += __shfl_xor_sync(0xffffffffu, ss, o);
        float rinv = 1.f / fmaxf(sqrtf(ss), 1e-12f);
        reinterpret_cast<float2*>(h_out + (size_t)item * DD)[lane] = h;
        __half2 hn = __floats2half2_rn(h.x * rinv, h.y * rinv);
        *reinterpret_cast<__half2*>(&sHn[w][t * HN_STRIDE + lane * 2]) = hn;
    }
    __syncwarp();

    // ---- stage 2: tcq over [ipre rows 0-7 ; hnorm rows 8-15] ----
    int gr = lane >> 2, tig = lane & 3;
    unsigned ra[4][4];
#pragma unroll
    for (int kt = 0; kt < 4; kt++) {
        const __half* x0 = g_ih_h + (size_t)(base + gr) * DD + kt * 16 + tig * 2;
        ra[kt][0] = *reinterpret_cast<const unsigned*>(x0);
        ra[kt][2] = *reinterpret_cast<const unsigned*>(x0 + 8);
        const __half* x1 = &sHn[w][gr * HN_STRIDE + kt * 16 + tig * 2];
        ra[kt][1] = *reinterpret_cast<const unsigned*>(x1);
        ra[kt][3] = *reinterpret_cast<const unsigned*>(x1 + 8);
    }

    float q0 = 0.f, q1 = 0.f;
#pragma unroll
    for (int nt = 0; nt < 8; nt++) {
        float c0 = 0.f, c1 = 0.f, c2 = 0.f, c3 = 0.f;
        int n = nt * 8 + gr;
#pragma unroll
        for (int kt = 0; kt < 4; kt++) {
            int k0 = kt * 16 + tig * 2;
            unsigned b0 = *reinterpret_cast<const unsigned*>(sWt + n * WT_STRIDE + k0);
            unsigned b1 = *reinterpret_cast<const unsigned*>(sWt + n * WT_STRIDE + k0 + 8);
            mma16816(c0, c1, c2, c3, ra[kt][0], ra[kt][1], ra[kt][2], ra[kt][3], b0, b1);
        }
        int col0 = nt * 8 + tig * 2, col1 = col0 + 1;
        q0 += ftanh(c0 + sb[col0]) * sw2[col0] + ftanh(c1 + sb[col1]) * sw2[col1];
        q1 += ftanh(c2 + sb[col0]) * sw2[col0] + ftanh(c3 + sb[col1]) * sw2[col1];
    }
    q0 += __shfl_xor_sync(0xffffffffu, q0, 1);
    q0 += __shfl_xor_sync(0xffffffffu, q0, 2);
    q1 += __shfl_xor_sync(0xffffffffu, q1, 1);
    q1 += __shfl_xor_sync(0xffffffffu, q1, 2);
    // q_ipre for item base+g at lane g*4 (q0); q_hnorm at lane g*4 (q1)

    // ---- stage 3: combine_item -> ig ----
#pragma unroll
    for (int t = 0; t < 8; t++) {
        float qa = __shfl_sync(0xffffffffu, q0, t * 4);
        float qb = __shfl_sync(0xffffffffu, q1, t * 4);
        float m = fmaxf(qa, qb);
        float e0 = __expf(qa - m), e1 = __expf(qb - m);
        float sinv = 1.f / (e0 + e1);
        float w0 = e0 * sinv, w1 = e1 * sinv;
        int item = base + t;
        __half2 ia = *reinterpret_cast<const __half2*>(g_ih_h + (size_t)item * DD + lane * 2);
        float2 a = __half22float2(ia);
        float2 n = __half22float2(*reinterpret_cast<const __half2*>(&sHn[w][t * HN_STRIDE + lane * 2]));
        float2 r = make_float2(w0 * a.x + w1 * n.x, w0 * a.y + w1 * n.y);
        reinterpret_cast<float2*>(ig + (size_t)item * DD)[lane] = r;
    }
}

extern "C" void kernel_launch(void* const* d_in, const int* in_sizes, int n_in,
                              void* d_out, int out_size) {
    const float* user_emb = (const float*)d_in[0];
    const float* item_emb = (const float*)d_in[1];
    const float* Wq1 = (const float*)d_in[2];
    const float* bq1 = (const float*)d_in[3];
    const float* wq2 = (const float*)d_in[4];
    const float* Wc1 = (const float*)d_in[5];
    const float* bc1 = (const float*)d_in[6];
    const float* wc2 = (const float*)d_in[7];
    const float* adj_vals = (const float*)d_in[8];
    const float* img_vals = (const float*)d_in[9];
    const float* txt_vals = (const float*)d_in[10];
    const int* adj_rows = (const int*)d_in[11];
    const int* adj_cols = (const int*)d_in[12];
    const int* img_rows = (const int*)d_in[13];
    const int* img_cols = (const int*)d_in[14];
    const int* txt_rows = (const int*)d_in[15];
    const int* txt_cols = (const int*)d_in[16];

    float* out = (float*)d_out;
    float* out_ug  = out + OFF_UG;
    float* out_ig  = out + OFF_IG;
    float* out_img = out + OFF_IMG;
    float* out_txt = out + OFF_TXT;
    float* out_h   = out + OFF_H;

    const int T = 256;

    int* cnt; cudaGetSymbolAddress((void**)&cnt, g_cnt);

    // 0. zero counters
    cudaMemsetAsync(cnt, 0, (NT + 2 * NI) * sizeof(int));

    // 1. fp16 ego conversion + bucket builds
    k1_prep_kernel<<<CVT_B + BKT_B, T>>>(
        (const float4*)user_emb, (const float4*)item_emb,
        (const int4*)adj_rows, (const int4*)adj_cols, (const float4*)adj_vals,
        (const int4*)img_rows, (const int4*)img_cols, (const float4*)img_vals,
        (const int4*)txt_rows, (const int4*)txt_cols, (const float4*)txt_vals);

    // 2. adj layer 1 + modal gathers
    {
        int nwarps = NT / 2 + NI;
        k2_gather_kernel<<<(nwarps + 7) / 8, T>>>(out_img, out_txt);
    }

    // 3. modal queries (tcq blocks first) || adj layer 2 + final averaging
    {
        int adj_blocks = (NT / 2 + 7) / 8;   // 6875
        k3_fused_kernel<<<TCQ_BLOCKS + adj_blocks, T>>>(out_img, Wq1, bq1, wq2,
                                                        (const float4*)user_emb,
                                                        (const float4*)item_emb, out_ug);
    }

    // 4. fused tail: combine_mm + item tcq + combine_item
    k4_tail_kernel<<<K4_BLOCKS, 128>>>(out_img, out_txt, Wc1, bc1, wc2, out_h, out_ig);

    (void)in_sizes; (void)n_in; (void)out_size;
}

// round 17
// speedup vs baseline: 1.0953x; 1.0301x over previous
#include <cuda_runtime.h>
#include <cuda_fp16.h>

#define NU 80000
#define NI 30000
#define NT 110000   // NU + NI
#define DD 64
#define NNZ_ADJ 2000000
#define NNZ_MM  300000

#define ADJ_CAP 64
#define MM_CAP  48

// out layout (float offsets)
#define OFF_UG   0
#define OFF_IG   (NU*DD)
#define OFF_IMG  (OFF_IG + NI*DD)
#define OFF_TXT  (OFF_IMG + NI*DD)
#define OFF_H    (OFF_TXT + NI*DD)

// ---------------- scratch ----------------
__device__ __half g_ego_h[NT*DD];    // fp16 [user_emb ; item_emb]
__device__ __half g_cur1_h[NT*DD];   // fp16 layer-1 adj output
__device__ __half g_ih_h[NI*DD];     // fp16 ipre for item tcq
__device__ float  g_q[2*NI];         // modal query outputs

__device__ int  g_cnt[NT + 2*NI];
__device__ int2 g_adj_pairs[(size_t)NT * ADJ_CAP];
__device__ int2 g_img_pairs[(size_t)NI * MM_CAP];
__device__ int2 g_txt_pairs[(size_t)NI * MM_CAP];

// ---------------- bucket build (4 edges/thread) ----------------
__device__ __forceinline__ void bucket4(int4 r, int4 c, float4 v,
                                        int* __restrict__ counts, int2* __restrict__ pairs,
                                        int cap) {
    int p0 = atomicAdd(&counts[r.x], 1);
    int p1 = atomicAdd(&counts[r.y], 1);
    int p2 = atomicAdd(&counts[r.z], 1);
    int p3 = atomicAdd(&counts[r.w], 1);
    if (p0 < cap) pairs[(size_t)r.x * cap + p0] = make_int2(c.x, __float_as_int(v.x));
    if (p1 < cap) pairs[(size_t)r.y * cap + p1] = make_int2(c.y, __float_as_int(v.y));
    if (p2 < cap) pairs[(size_t)r.z * cap + p2] = make_int2(c.z, __float_as_int(v.z));
    if (p3 < cap) pairs[(size_t)r.w * cap + p3] = make_int2(c.w, __float_as_int(v.w));
}

#define TA (NNZ_ADJ/4)
#define TM (NNZ_MM/4)
#define CVT_B ((NT*(DD/4) + 255)/256)
#define BKT_B ((TA + 2*TM + 255)/256)

// ---------------- K1: fp16 ego conversion + bucket builds (fused) ----------------
__global__ __launch_bounds__(256) void k1_prep_kernel(
        const float4* __restrict__ ue, const float4* __restrict__ ie,
        const int4* __restrict__ ar, const int4* __restrict__ ac, const float4* __restrict__ av,
        const int4* __restrict__ ir, const int4* __restrict__ ic, const float4* __restrict__ iv,
        const int4* __restrict__ tr, const int4* __restrict__ tc, const float4* __restrict__ tv) {
    if (blockIdx.x < CVT_B) {
        int i = blockIdx.x * blockDim.x + threadIdx.x;
        if (i >= NT * (DD / 4)) return;
        float4 v = (i < NU * (DD / 4)) ? ue[i] : ie[i - NU * (DD / 4)];
        __half2 h01 = __floats2half2_rn(v.x, v.y);
        __half2 h23 = __floats2half2_rn(v.z, v.w);
        uint2 u;
        u.x = *reinterpret_cast<unsigned*>(&h01);
        u.y = *reinterpret_cast<unsigned*>(&h23);
        reinterpret_cast<uint2*>(g_ego_h)[i] = u;
    } else {
        int t = (blockIdx.x - CVT_B) * blockDim.x + threadIdx.x;
        if (t < TA) {
            bucket4(ar[t], ac[t], av[t], g_cnt, g_adj_pairs, ADJ_CAP);
        } else if (t < TA + TM) {
            int e = t - TA;
            bucket4(ir[e], ic[e], iv[e], g_cnt + NT, g_img_pairs, MM_CAP);
        } else if (t < TA + 2 * TM) {
            int e = t - TA - TM;
            bucket4(tr[e], tc[e], tv[e], g_cnt + NT + NI, g_txt_pairs, MM_CAP);
        }
    }
}

// ---------------- paired-row fp16 gather (R12-proven) ----------------
__device__ __forceinline__ float4 gather_row_pair_h(const int2* __restrict__ p_my, int cnt_my,
                                                    int cnt_max, const __half* __restrict__ x,
                                                    int hl) {
    float4 a = make_float4(0.f, 0.f, 0.f, 0.f);
    for (int base = 0; base < cnt_max; base += 16) {
        int j = base + hl;
        int2 pr = (j < cnt_my) ? p_my[j] : make_int2(0, 0);
        int m4 = (min(cnt_max - base, 16) + 3) & ~3;
        for (int k = 0; k < m4; k += 4) {
#pragma unroll
            for (int kk = 0; kk < 4; kk++) {
                int   c = __shfl_sync(0xffffffffu, pr.x, k + kk, 16);
                float v = __int_as_float(__shfl_sync(0xffffffffu, pr.y, k + kk, 16));
                uint2 u = __ldg(reinterpret_cast<const uint2*>(x + (size_t)c * DD) + hl);
                __half2 h01 = *reinterpret_cast<__half2*>(&u.x);
                __half2 h23 = *reinterpret_cast<__half2*>(&u.y);
                float2 f01 = __half22float2(h01);
                float2 f23 = __half22float2(h23);
                a.x = fmaf(v, f01.x, a.x);
                a.y = fmaf(v, f01.y, a.y);
                a.z = fmaf(v, f23.x, a.z);
                a.w = fmaf(v, f23.y, a.w);
            }
        }
    }
    return a;
}

__device__ __forceinline__ void store_half4(__half* __restrict__ dst, int hl, float4 a) {
    __half2 h01 = __floats2half2_rn(a.x, a.y);
    __half2 h23 = __floats2half2_rn(a.z, a.w);
    uint2 u;
    u.x = *reinterpret_cast<unsigned*>(&h01);
    u.y = *reinterpret_cast<unsigned*>(&h23);
    reinterpret_cast<uint2*>(dst)[hl] = u;
}

// ---------------- K2: adj layer 1 + modal gathers ----------------
__global__ __launch_bounds__(256) void k2_gather_kernel(float* __restrict__ out_img,
                                                        float* __restrict__ out_txt) {
    int w = (blockIdx.x * blockDim.x + threadIdx.x) >> 5;
    int lane = threadIdx.x & 31;
    int half = lane >> 4, hl = lane & 15;
    if (w < NT / 2) {
        int row = w * 2 + half;
        int cnt = min(g_cnt[row], ADJ_CAP);
        int cmax = max(cnt, __shfl_xor_sync(0xffffffffu, cnt, 16));
        float4 a = gather_row_pair_h(g_adj_pairs + (size_t)row * ADJ_CAP, cnt, cmax, g_ego_h, hl);
        store_half4(g_cur1_h + (size_t)row * DD, hl, a);
    } else if (w < NT / 2 + NI) {
        int mrow = (w - NT / 2) * 2 + half;
        bool is_img = mrow < NI;
        int row = is_img ? mrow : mrow - NI;
        int cnt = min(is_img ? g_cnt[NT + row] : g_cnt[NT + NI + row], MM_CAP);
        int cmax = max(cnt, __shfl_xor_sync(0xffffffffu, cnt, 16));
        const int2* p = (is_img ? g_img_pairs : g_txt_pairs) + (size_t)row * MM_CAP;
        float4 a = gather_row_pair_h(p, cnt, cmax, g_ego_h + (size_t)NU * DD, hl);
        float* dst = (is_img ? out_img : out_txt) + (size_t)row * DD;
        reinterpret_cast<float4*>(dst)[hl] = a;
    }
}

// ============================================================================
// MMA helpers
// ============================================================================
__device__ __forceinline__ unsigned f2h2(float x, float y) {
    __half2 h = __floats2half2_rn(x, y);
    return *reinterpret_cast<unsigned*>(&h);
}

__device__ __forceinline__ float ftanh(float x) {
    x = fminf(fmaxf(x, -15.f), 15.f);
    float e = __expf(2.f * x);
    return (e - 1.f) / (e + 1.f);
}

__device__ __forceinline__ void mma16816(float& c0, float& c1, float& c2, float& c3,
                                         unsigned a0, unsigned a1, unsigned a2, unsigned a3,
                                         unsigned b0, unsigned b1) {
    asm volatile("mma.sync.aligned.m16n8k16.row.col.f32.f16.f16.f32 "
                 "{%0,%1,%2,%3}, {%4,%5,%6,%7}, {%8,%9}, {%0,%1,%2,%3};"
                 : "+f"(c0), "+f"(c1), "+f"(c2), "+f"(c3)
                 : "r"(a0), "r"(a1), "r"(a2), "r"(a3), "r"(b0), "r"(b1));
}

#define WT_STRIDE 72
#define TCQ_ROWS_PER_BLOCK 64
#define TCQ_BLOCKS ((2*NI + TCQ_ROWS_PER_BLOCK - 1) / TCQ_ROWS_PER_BLOCK)   // 938

// ---------------- tcq1 body: modal queries over fp32 img|txt -> g_q ----------------
__device__ void tcq_body_f32(const float* __restrict__ X, int nrows,
                             const float* __restrict__ W, const float* __restrict__ b,
                             const float* __restrict__ w2, float* __restrict__ qout, int bid) {
    __shared__ __half sWt[64 * WT_STRIDE];
    __shared__ float sb[64];
    __shared__ float sw2[64];
    for (int i = threadIdx.x; i < 4096; i += 256) {
        int k = i >> 6, n = i & 63;
        sWt[n * WT_STRIDE + k] = __float2half(W[i]);
    }
    if (threadIdx.x < 64) { sb[threadIdx.x] = b[threadIdx.x]; sw2[threadIdx.x] = w2[threadIdx.x]; }
    __syncthreads();

    int w = threadIdx.x >> 5, lane = threadIdx.x & 31;
    int gr = lane >> 2, tig = lane & 3;
    int base = bid * TCQ_ROWS_PER_BLOCK + w * 8;
    if (base >= nrows) return;
    int r0 = base + gr;

    unsigned ra[4][2];
#pragma unroll
    for (int kt = 0; kt < 4; kt++) {
        const float* x0 = X + (size_t)r0 * 64 + kt * 16 + tig * 2;
        float2 f0 = *reinterpret_cast<const float2*>(x0);
        float2 f2 = *reinterpret_cast<const float2*>(x0 + 8);
        ra[kt][0] = f2h2(f0.x, f0.y);
        ra[kt][1] = f2h2(f2.x, f2.y);
    }

    float q0 = 0.f;
#pragma unroll
    for (int nt = 0; nt < 8; nt++) {
        float c0 = 0.f, c1 = 0.f, c2 = 0.f, c3 = 0.f;
        int n = nt * 8 + gr;
#pragma unroll
        for (int kt = 0; kt < 4; kt++) {
            int k0 = kt * 16 + tig * 2;
            unsigned b0 = *reinterpret_cast<const unsigned*>(sWt + n * WT_STRIDE + k0);
            unsigned b1 = *reinterpret_cast<const unsigned*>(sWt + n * WT_STRIDE + k0 + 8);
            mma16816(c0, c1, c2, c3, ra[kt][0], 0u, ra[kt][1], 0u, b0, b1);
        }
        int col0 = nt * 8 + tig * 2, col1 = col0 + 1;
        q0 += ftanh(c0 + sb[col0]) * sw2[col0] + ftanh(c1 + sb[col1]) * sw2[col1];
    }
    q0 += __shfl_xor_sync(0xffffffffu, q0, 1);
    q0 += __shfl_xor_sync(0xffffffffu, q0, 2);
    if (tig == 0) qout[r0] = q0;
}

// ---------------- adj2 body (paired-row gather + final averaging) ----------------
__device__ void adj2_body(const float4* __restrict__ ue, const float4* __restrict__ ie,
                          float* __restrict__ ug, int bid) {
    int w = (bid * 256 + (int)threadIdx.x) >> 5;
    int lane = threadIdx.x & 31;
    int half = lane >> 4, hl = lane & 15;
    if (w >= NT / 2) return;
    int row = w * 2 + half;
    int cnt = min(g_cnt[row], ADJ_CAP);
    int cmax = max(cnt, __shfl_xor_sync(0xffffffffu, cnt, 16));
    float4 s = gather_row_pair_h(g_adj_pairs + (size_t)row * ADJ_CAP, cnt, cmax, g_cur1_h, hl);
    const float kk = 1.f / 3.f;
    uint2 u = reinterpret_cast<const uint2*>(g_cur1_h + (size_t)row * DD)[hl];
    float2 c01 = __half22float2(*reinterpret_cast<__half2*>(&u.x));
    float2 c23 = __half22float2(*reinterpret_cast<__half2*>(&u.y));
    float4 e = (row < NU) ? ue[row * (DD / 4) + hl]
                          : ie[(row - NU) * (DD / 4) + hl];
    float4 r = make_float4((e.x + c01.x + s.x) * kk, (e.y + c01.y + s.y) * kk,
                           (e.z + c23.x + s.z) * kk, (e.w + c23.y + s.w) * kk);
    if (row < NU) {
        reinterpret_cast<float4*>(ug + (size_t)row * DD)[hl] = r;
    } else {
        store_half4(g_ih_h + (size_t)(row - NU) * DD, hl, r);   // ipre (fp16)
    }
}

// ---------------- K3: tcq1 (blocks [0,TCQ_BLOCKS)) || adj2 (rest) ----------------
__global__ __launch_bounds__(256) void k3_fused_kernel(const float* __restrict__ Xmod,
                                                       const float* __restrict__ Wq1,
                                                       const float* __restrict__ bq1,
                                                       const float* __restrict__ wq2,
                                                       const float4* __restrict__ ue,
                                                       const float4* __restrict__ ie,
                                                       float* __restrict__ ug) {
    if (blockIdx.x < TCQ_BLOCKS) {
        tcq_body_f32(Xmod, 2 * NI, Wq1, bq1, wq2, g_q, blockIdx.x);
    } else {
        adj2_body(ue, ie, ug, blockIdx.x - TCQ_BLOCKS);
    }
}

// ============================================================================
// K4 (fused tail): warp owns 8 items through all three stages; elementwise
// stages parallelized across half-warps (2 items per iteration, float4 lanes).
// ============================================================================
#define K4_ITEMS 32
#define K4_BLOCKS ((NI + K4_ITEMS - 1) / K4_ITEMS)   // 938
#define HN_STRIDE 72   // padded hnorm smem row (halfs)

__global__ __launch_bounds__(128) void k4_tail_kernel(const float* __restrict__ img,
                                                      const float* __restrict__ txt,
                                                      const float* __restrict__ Wc1,
                                                      const float* __restrict__ bc1,
                                                      const float* __restrict__ wc2,
                                                      float* __restrict__ h_out,
                                                      float* __restrict__ ig) {
    __shared__ __half sWt[64 * WT_STRIDE];
    __shared__ float sb[64];
    __shared__ float sw2[64];
    __shared__ __half sHn[4][8 * HN_STRIDE];
    for (int i = threadIdx.x; i < 4096; i += 128) {
        int k = i >> 6, n = i & 63;
        sWt[n * WT_STRIDE + k] = __float2half(Wc1[i]);
    }
    if (threadIdx.x < 64) { sb[threadIdx.x] = bc1[threadIdx.x]; sw2[threadIdx.x] = wc2[threadIdx.x]; }
    __syncthreads();

    int w = threadIdx.x >> 5, lane = threadIdx.x & 31;
    int half = lane >> 4, hl = lane & 15;
    int base = blockIdx.x * K4_ITEMS + w * 8;   // NI % 8 == 0
    if (base >= NI) return;

    // ---- stage 1: combine_mm, 2 items per iteration (one per half-warp) ----
#pragma unroll
    for (int t = 0; t < 8; t += 2) {
        int it = t + half;
        int item = base + it;
        float qi = g_q[item], qt = g_q[NI + item];
        float m = fmaxf(qi, qt);
        float e0 = __expf(qi - m), e1 = __expf(qt - m);
        float sinv = 1.f / (e0 + e1);
        float w0 = e0 * sinv, w1 = e1 * sinv;
        float4 iv = reinterpret_cast<const float4*>(img + (size_t)item * DD)[hl];
        float4 tv = reinterpret_cast<const float4*>(txt + (size_t)item * DD)[hl];
        float4 h = make_float4(w0 * iv.x + w1 * tv.x, w0 * iv.y + w1 * tv.y,
                               w0 * iv.z + w1 * tv.z, w0 * iv.w + w1 * tv.w);
        float ss = h.x * h.x + h.y * h.y + h.z * h.z + h.w * h.w;
#pragma unroll
        for (int o = 1; o < 16; o <<= 1) ss += __shfl_xor_sync(0xffffffffu, ss, o, 16);
        float rinv = 1.f / fmaxf(sqrtf(ss), 1e-12f);
        reinterpret_cast<float4*>(h_out + (size_t)item * DD)[hl] = h;
        __half2 h01 = __floats2half2_rn(h.x * rinv, h.y * rinv);
        __half2 h23 = __floats2half2_rn(h.z * rinv, h.w * rinv);
        uint2 uo;
        uo.x = *reinterpret_cast<unsigned*>(&h01);
        uo.y = *reinterpret_cast<unsigned*>(&h23);
        *reinterpret_cast<uint2*>(&sHn[w][it * HN_STRIDE + hl * 4]) = uo;
    }
    __syncwarp();

    // ---- stage 2: tcq over [ipre rows 0-7 ; hnorm rows 8-15] ----
    int gr = lane >> 2, tig = lane & 3;
    unsigned ra[4][4];
#pragma unroll
    for (int kt = 0; kt < 4; kt++) {
        const __half* x0 = g_ih_h + (size_t)(base + gr) * DD + kt * 16 + tig * 2;
        ra[kt][0] = *reinterpret_cast<const unsigned*>(x0);
        ra[kt][2] = *reinterpret_cast<const unsigned*>(x0 + 8);
        const __half* x1 = &sHn[w][gr * HN_STRIDE + kt * 16 + tig * 2];
        ra[kt][1] = *reinterpret_cast<const unsigned*>(x1);
        ra[kt][3] = *reinterpret_cast<const unsigned*>(x1 + 8);
    }

    float q0 = 0.f, q1 = 0.f;
#pragma unroll
    for (int nt = 0; nt < 8; nt++) {
        float c0 = 0.f, c1 = 0.f, c2 = 0.f, c3 = 0.f;
        int n = nt * 8 + gr;
#pragma unroll
        for (int kt = 0; kt < 4; kt++) {
            int k0 = kt * 16 + tig * 2;
            unsigned b0 = *reinterpret_cast<const unsigned*>(sWt + n * WT_STRIDE + k0);
            unsigned b1 = *reinterpret_cast<const unsigned*>(sWt + n * WT_STRIDE + k0 + 8);
            mma16816(c0, c1, c2, c3, ra[kt][0], ra[kt][1], ra[kt][2], ra[kt][3], b0, b1);
        }
        int col0 = nt * 8 + tig * 2, col1 = col0 + 1;
        q0 += ftanh(c0 + sb[col0]) * sw2[col0] + ftanh(c1 + sb[col1]) * sw2[col1];
        q1 += ftanh(c2 + sb[col0]) * sw2[col0] + ftanh(c3 + sb[col1]) * sw2[col1];
    }
    q0 += __shfl_xor_sync(0xffffffffu, q0, 1);
    q0 += __shfl_xor_sync(0xffffffffu, q0, 2);
    q1 += __shfl_xor_sync(0xffffffffu, q1, 1);
    q1 += __shfl_xor_sync(0xffffffffu, q1, 2);
    // q_ipre for item base+g at lane g*4 (q0); q_hnorm at lane g*4 (q1)

    // ---- stage 3: combine_item -> ig, 2 items per iteration ----
#pragma unroll
    for (int t = 0; t < 8; t += 2) {
        int it = t + half;
        float qa = __shfl_sync(0xffffffffu, q0, it * 4);
        float qb = __shfl_sync(0xffffffffu, q1, it * 4);
        float m = fmaxf(qa, qb);
        float e0 = __expf(qa - m), e1 = __expf(qb - m);
        float sinv = 1.f / (e0 + e1);
        float w0 = e0 * sinv, w1 = e1 * sinv;
        int item = base + it;
        uint2 ua = *reinterpret_cast<const uint2*>(g_ih_h + (size_t)item * DD + hl * 4);
        uint2 un = *reinterpret_cast<const uint2*>(&sHn[w][it * HN_STRIDE + hl * 4]);
        float2 a01 = __half22float2(*reinterpret_cast<__half2*>(&ua.x));
        float2 a23 = __half22float2(*reinterpret_cast<__half2*>(&ua.y));
        float2 n01 = __half22float2(*reinterpret_cast<__half2*>(&un.x));
        float2 n23 = __half22float2(*reinterpret_cast<__half2*>(&un.y));
        float4 r = make_float4(w0 * a01.x + w1 * n01.x, w0 * a01.y + w1 * n01.y,
                               w0 * a23.x + w1 * n23.x, w0 * a23.y + w1 * n23.y);
        reinterpret_cast<float4*>(ig + (size_t)item * DD)[hl] = r;
    }
}

extern "C" void kernel_launch(void* const* d_in, const int* in_sizes, int n_in,
                              void* d_out, int out_size) {
    const float* user_emb = (const float*)d_in[0];
    const float* item_emb = (const float*)d_in[1];
    const float* Wq1 = (const float*)d_in[2];
    const float* bq1 = (const float*)d_in[3];
    const float* wq2 = (const float*)d_in[4];
    const float* Wc1 = (const float*)d_in[5];
    const float* bc1 = (const float*)d_in[6];
    const float* wc2 = (const float*)d_in[7];
    const float* adj_vals = (const float*)d_in[8];
    const float* img_vals = (const float*)d_in[9];
    const float* txt_vals = (const float*)d_in[10];
    const int* adj_rows = (const int*)d_in[11];
    const int* adj_cols = (const int*)d_in[12];
    const int* img_rows = (const int*)d_in[13];
    const int* img_cols = (const int*)d_in[14];
    const int* txt_rows = (const int*)d_in[15];
    const int* txt_cols = (const int*)d_in[16];

    float* out = (float*)d_out;
    float* out_ug  = out + OFF_UG;
    float* out_ig  = out + OFF_IG;
    float* out_img = out + OFF_IMG;
    float* out_txt = out + OFF_TXT;
    float* out_h   = out + OFF_H;

    const int T = 256;

    int* cnt; cudaGetSymbolAddress((void**)&cnt, g_cnt);

    // 0. zero counters
    cudaMemsetAsync(cnt, 0, (NT + 2 * NI) * sizeof(int));

    // 1. fp16 ego conversion + bucket builds
    k1_prep_kernel<<<CVT_B + BKT_B, T>>>(
        (const float4*)user_emb, (const float4*)item_emb,
        (const int4*)adj_rows, (const int4*)adj_cols, (const float4*)adj_vals,
        (const int4*)img_rows, (const int4*)img_cols, (const float4*)img_vals,
        (const int4*)txt_rows, (const int4*)txt_cols, (const float4*)txt_vals);

    // 2. adj layer 1 + modal gathers
    {
        int nwarps = NT / 2 + NI;
        k2_gather_kernel<<<(nwarps + 7) / 8, T>>>(out_img, out_txt);
    }

    // 3. modal queries (tcq blocks first) || adj layer 2 + final averaging
    {
        int adj_blocks = (NT / 2 + 7) / 8;   // 6875
        k3_fused_kernel<<<TCQ_BLOCKS + adj_blocks, T>>>(out_img, Wq1, bq1, wq2,
                                                        (const float4*)user_emb,
                                                        (const float4*)item_emb, out_ug);
    }

    // 4. fused tail: combine_mm + item tcq + combine_item (half-warp parallel stages)
    k4_tail_kernel<<<K4_BLOCKS, 128>>>(out_img, out_txt, Wc1, bc1, wc2, out_h, out_ig);

    (void)in_sizes; (void)n_in; (void)out_size;
}